// round 15
// baseline (speedup 1.0000x reference)
#include <cuda_runtime.h>
#include <math.h>
#include <stdint.h>

#define BB 64
#define LC 1024
#define LQ 128
#define DD 128
#define NEG (-1e9f)

// ---------------- device scratch ----------------
__device__ float g_S[(size_t)BB * LC * LQ];      // X = exp(S), 32 MB
__device__ float g_rinv[BB * LC];
__device__ float g_cps[BB * 8 * LQ];
__device__ float g_cinv[BB * LQ];
__device__ float g_V2p[(size_t)4 * BB * LQ * DD];
__device__ float g_V2[BB * LQ * DD];

// ---------------- helpers ----------------
__device__ __forceinline__ void split_tf32(float x, uint32_t& hi, uint32_t& lo) {
    asm("cvt.rna.tf32.f32 %0, %1;" : "=r"(hi) : "f"(x));
    float r = x - __uint_as_float(hi);
    asm("cvt.rna.tf32.f32 %0, %1;" : "=r"(lo) : "f"(r));
}
__device__ __forceinline__ uint32_t cvt_tf32(float x) {
    uint32_t h;
    asm("cvt.rna.tf32.f32 %0, %1;" : "=r"(h) : "f"(x));
    return h;
}
__device__ __forceinline__ void mma8(float* d, const uint32_t* a, const uint32_t* b) {
    asm("mma.sync.aligned.m16n8k8.row.col.f32.tf32.tf32.f32 "
        "{%0,%1,%2,%3}, {%4,%5,%6,%7}, {%8,%9}, {%0,%1,%2,%3};"
        : "+f"(d[0]), "+f"(d[1]), "+f"(d[2]), "+f"(d[3])
        : "r"(a[0]), "r"(a[1]), "r"(a[2]), "r"(a[3]), "r"(b[0]), "r"(b[1]));
}
__device__ __forceinline__ void mma3(float* d, const uint32_t* ah, const uint32_t* al,
                                     const uint32_t* bh, const uint32_t* bl) {
    mma8(d, ah, bh);
    mma8(d, ah, bl);
    mma8(d, al, bh);
}
__device__ __forceinline__ void cpa16(uint32_t dst, const float* src) {
    asm volatile("cp.async.cg.shared.global [%0], [%1], 16;" :: "r"(dst), "l"(src));
}
#define CP_COMMIT() asm volatile("cp.async.commit_group;" ::: "memory")
#define CP_WAIT(n)  asm volatile("cp.async.wait_group %0;" :: "n"(n) : "memory")

// ================= K1: S GEMM (3xTF32, cp.async) + fused dots + stats ====
#define S_DYN (4 * 128 * 36 * 4)
__global__ __launch_bounds__(256, 2) void s_kernel(
    const float* __restrict__ Cg, const float* __restrict__ Qg,
    const float* __restrict__ w_mul, const float* __restrict__ w_c,
    const float* __restrict__ w_q, const float* __restrict__ bias,
    const int* __restrict__ Qmask, const int* __restrict__ Cmask) {
    extern __shared__ float dynf[];
    float* Ab[2] = {dynf, dynf + 128 * 36};
    float* Qb2[2] = {dynf + 2 * 128 * 36, dynf + 3 * 128 * 36};
    float* Ss = dynf;                // [128][132] epilogue alias
    __shared__ float s_cd[128], s_qd[128], s_wm[128], s_wc[128], s_wq[128];
    __shared__ float s_s2[128];
    __shared__ int s_qm[128], s_cm[128];

    int bx = blockIdx.x;
    int b = bx >> 3, tile = bx & 7, i0 = tile << 7;
    int t = threadIdx.x, wid = t >> 5, lane = t & 31;
    int g = lane >> 2, tg = lane & 3;
    int wm_ = wid & 3, wn = wid >> 2;
    int mb = wm_ << 5;
    int jb = wn << 6;

    if (t < 128) {
        s_qm[t] = Qmask[b * LQ + t];
        s_cm[t] = Cmask[b * LC + i0 + t];
        s_wm[t] = w_mul[t];
        s_wc[t] = w_c[t];
        s_wq[t] = w_q[t];
    }

    const float* Cb = Cg + ((size_t)b * LC + i0) * DD;
    const float* Qb = Qg + (size_t)b * LQ * DD;
    uint32_t aB[2], qB[2];
    aB[0] = (uint32_t)__cvta_generic_to_shared(Ab[0]);
    aB[1] = (uint32_t)__cvta_generic_to_shared(Ab[1]);
    qB[0] = (uint32_t)__cvta_generic_to_shared(Qb2[0]);
    qB[1] = (uint32_t)__cvta_generic_to_shared(Qb2[1]);

    float acc[2][8][4];
    #pragma unroll
    for (int mt = 0; mt < 2; mt++)
        #pragma unroll
        for (int nt = 0; nt < 8; nt++)
            #pragma unroll
            for (int e = 0; e < 4; e++) acc[mt][nt][e] = 0.f;

    int row0 = t >> 3, ch = t & 7;
    float cdp[4] = {0.f, 0.f, 0.f, 0.f};
    float qdp[4] = {0.f, 0.f, 0.f, 0.f};

    #define S_ISSUE(buf, kk) {                                              \
        _Pragma("unroll")                                                   \
        for (int u = 0; u < 4; u++) {                                       \
            int row = row0 + u * 32;                                        \
            cpa16(aB[buf] + (row * 36 + ch * 4) * 4, Cb + (size_t)row * DD + (kk) + ch * 4); \
            cpa16(qB[buf] + (row * 36 + ch * 4) * 4, Qb + (size_t)row * DD + (kk) + ch * 4); \
        }                                                                   \
        CP_COMMIT(); }

    S_ISSUE(0, 0)
    #pragma unroll
    for (int s = 0; s < 4; s++) {
        if (s < 3) S_ISSUE((s + 1) & 1, (s + 1) * 32)
        if (s < 3) { CP_WAIT(1); } else { CP_WAIT(0); }
        __syncthreads();
        const float* As = Ab[s & 1];
        const float* Qs = Qb2[s & 1];
        int kk = s * 32;
        {   // fused dots partials
            float4 wc = *(const float4*)&s_wc[kk + ch * 4];
            float4 wq = *(const float4*)&s_wq[kk + ch * 4];
            #pragma unroll
            for (int u = 0; u < 4; u++) {
                int row = row0 + u * 32;
                float4 a = *(const float4*)&As[row * 36 + ch * 4];
                cdp[u] += a.x * wc.x + a.y * wc.y + a.z * wc.z + a.w * wc.w;
                float4 q = *(const float4*)&Qs[row * 36 + ch * 4];
                qdp[u] += q.x * wq.x + q.y * wq.y + q.z * wq.z + q.w * wq.w;
            }
        }
        #pragma unroll
        for (int k8 = 0; k8 < 4; k8++) {
            int kb = k8 << 3;
            float wm0 = s_wm[kk + kb + tg], wm1 = s_wm[kk + kb + tg + 4];
            uint32_t ah[2][4], al[2][4];
            #pragma unroll
            for (int mt = 0; mt < 2; mt++) {
                int m0 = mb + mt * 16;
                split_tf32(As[(m0 + g) * 36 + kb + tg] * wm0,         ah[mt][0], al[mt][0]);
                split_tf32(As[(m0 + g + 8) * 36 + kb + tg] * wm0,     ah[mt][1], al[mt][1]);
                split_tf32(As[(m0 + g) * 36 + kb + tg + 4] * wm1,     ah[mt][2], al[mt][2]);
                split_tf32(As[(m0 + g + 8) * 36 + kb + tg + 4] * wm1, ah[mt][3], al[mt][3]);
            }
            #pragma unroll
            for (int nt = 0; nt < 8; nt++) {
                uint32_t bh[2], bl[2];
                split_tf32(Qs[(jb + nt * 8 + g) * 36 + kb + tg],     bh[0], bl[0]);
                split_tf32(Qs[(jb + nt * 8 + g) * 36 + kb + tg + 4], bh[1], bl[1]);
                mma3(acc[0][nt], ah[0], al[0], bh, bl);
                mma3(acc[1][nt], ah[1], al[1], bh, bl);
            }
        }
        __syncthreads();
    }

    // reduce dots over the 8 threads sharing a row
    #pragma unroll
    for (int u = 0; u < 4; u++) {
        #pragma unroll
        for (int o = 1; o < 8; o <<= 1) {
            cdp[u] += __shfl_xor_sync(0xffffffffu, cdp[u], o);
            qdp[u] += __shfl_xor_sync(0xffffffffu, qdp[u], o);
        }
        if (ch == 0) {
            s_cd[row0 + u * 32] = cdp[u];
            s_qd[row0 + u * 32] = qdp[u];
        }
    }
    __syncthreads();

    // finalize S into Ss
    {
        float bi = bias[0];
        #pragma unroll
        for (int mt = 0; mt < 2; mt++) {
            int m0 = mb + mt * 16;
            float cd0 = s_cd[m0 + g] + bi, cd1 = s_cd[m0 + g + 8] + bi;
            #pragma unroll
            for (int nt = 0; nt < 8; nt++) {
                int c0 = jb + nt * 8 + 2 * tg;
                float q0 = s_qd[c0], q1 = s_qd[c0 + 1];
                Ss[(m0 + g) * 132 + c0]     = acc[mt][nt][0] + cd0 + q0;
                Ss[(m0 + g) * 132 + c0 + 1] = acc[mt][nt][1] + cd0 + q1;
                Ss[(m0 + g + 8) * 132 + c0]     = acc[mt][nt][2] + cd1 + q0;
                Ss[(m0 + g + 8) * 132 + c0 + 1] = acc[mt][nt][3] + cd1 + q1;
            }
        }
    }
    __syncthreads();

    // phase A: X = exp(S) -> Ss & g_S ; masked row sums
    {
        int i = t >> 1, j0 = (t & 1) << 6;
        float sm = 0.f;
        float* dst = g_S + ((size_t)(b * LC + i0 + i)) * LQ + j0;
        #pragma unroll
        for (int u = 0; u < 64; u += 4) {
            float4 v = *(const float4*)&Ss[i * 132 + j0 + u];
            int4 m = *(const int4*)&s_qm[j0 + u];
            float4 x = make_float4(__expf(v.x), __expf(v.y), __expf(v.z), __expf(v.w));
            *(float4*)&Ss[i * 132 + j0 + u] = x;
            *(float4*)(dst + u) = x;
            sm += (m.x ? x.x : 0.f) + (m.y ? x.y : 0.f)
                + (m.z ? x.z : 0.f) + (m.w ? x.w : 0.f);
        }
        sm += __shfl_xor_sync(0xffffffffu, sm, 1);
        if ((t & 1) == 0) g_rinv[b * LC + i0 + i] = 1.f / sm;
    }
    __syncthreads();

    // phase B: masked column partial sums
    {
        int j = t & 127, ih = t >> 7;
        float s = 0.f;
        #pragma unroll 8
        for (int r = 0; r < 64; r++) {
            int i = ih * 64 + r;
            s += s_cm[i] ? Ss[i * 132 + j] : 0.f;
        }
        if (ih == 1) s_s2[j] = s;
        __syncthreads();
        if (ih == 0)
            g_cps[(b * 8 + tile) * LQ + j] = s + s_s2[j];
    }
}

// ================= K2: merge column partial sums =================
__global__ __launch_bounds__(256) void colmerge_kernel() {
    int idx = blockIdx.x * blockDim.x + threadIdx.x;
    if (idx >= BB * LQ) return;
    int b = idx >> 7, j = idx & 127;
    float S = 0.f;
    #pragma unroll
    for (int g = 0; g < 8; g++) S += g_cps[(b * 8 + g) * LQ + j];
    g_cinv[idx] = 1.f / S;
}

// ================= K3: V2 partial (plain tf32, cp.async), split-K=4 ======
#define V2_DYN (4 * 32 * 136 * 4)
__global__ __launch_bounds__(256, 2) void v2_kernel(
    const float* __restrict__ Cg, const int* __restrict__ Cmask) {
    extern __shared__ float dynf[];
    float* Xb[2] = {dynf, dynf + 32 * 136};
    float* Cb2[2] = {dynf + 2 * 32 * 136, dynf + 3 * 32 * 136};
    __shared__ int s_cm[256];
    int b = blockIdx.x >> 2, gc = blockIdx.x & 3;
    int t = threadIdx.x, wid = t >> 5, lane = t & 31;
    int g = lane >> 2, tg = lane & 3;
    int wm_ = wid >> 1, wn = wid & 1;
    int mb0 = wm_ << 5;
    int nb = wn << 6;
    s_cm[t] = Cmask[b * LC + gc * 256 + t];

    float ci_[2][2];
    #pragma unroll
    for (int mt = 0; mt < 2; mt++) {
        ci_[mt][0] = g_cinv[b * LQ + mb0 + mt * 16 + g];
        ci_[mt][1] = g_cinv[b * LQ + mb0 + mt * 16 + g + 8];
    }

    const float* Sb = g_S + ((size_t)(b * LC + gc * 256)) * LQ;
    const float* Cb = Cg + ((size_t)(b * LC + gc * 256)) * DD;
    uint32_t xB[2], cB[2];
    xB[0] = (uint32_t)__cvta_generic_to_shared(Xb[0]);
    xB[1] = (uint32_t)__cvta_generic_to_shared(Xb[1]);
    cB[0] = (uint32_t)__cvta_generic_to_shared(Cb2[0]);
    cB[1] = (uint32_t)__cvta_generic_to_shared(Cb2[1]);

    float acc[2][8][4];
    #pragma unroll
    for (int mt = 0; mt < 2; mt++)
        #pragma unroll
        for (int nt = 0; nt < 8; nt++)
            #pragma unroll
            for (int e = 0; e < 4; e++) acc[mt][nt][e] = 0.f;

    #define V_ISSUE(buf, ik) {                                              \
        _Pragma("unroll")                                                   \
        for (int u = 0; u < 4; u++) {                                       \
            int gid = u * 256 + t, row = gid >> 5, ch = gid & 31;           \
            cpa16(xB[buf] + (row * 136 + ch * 4) * 4, Sb + (size_t)((ik) + row) * LQ + ch * 4); \
            cpa16(cB[buf] + (row * 136 + ch * 4) * 4, Cb + (size_t)((ik) + row) * DD + ch * 4); \
        }                                                                   \
        CP_COMMIT(); }

    V_ISSUE(0, 0)
    #pragma unroll
    for (int s = 0; s < 8; s++) {
        if (s < 7) V_ISSUE((s + 1) & 1, (s + 1) * 32)
        if (s < 7) { CP_WAIT(1); } else { CP_WAIT(0); }
        __syncthreads();
        const float* Xs = Xb[s & 1];
        const float* Cs = Cb2[s & 1];
        int ik = s * 32;
        #pragma unroll
        for (int k8 = 0; k8 < 4; k8++) {
            int kb = k8 << 3;
            float f0 = s_cm[ik + kb + tg] ? 1.f : 0.f;
            float f1 = s_cm[ik + kb + tg + 4] ? 1.f : 0.f;
            uint32_t a[2][4];
            #pragma unroll
            for (int mt = 0; mt < 2; mt++) {
                int m0 = mb0 + mt * 16;
                a[mt][0] = cvt_tf32(Xs[(kb + tg) * 136 + m0 + g] * (f0 * ci_[mt][0]));
                a[mt][1] = cvt_tf32(Xs[(kb + tg) * 136 + m0 + g + 8] * (f0 * ci_[mt][1]));
                a[mt][2] = cvt_tf32(Xs[(kb + tg + 4) * 136 + m0 + g] * (f1 * ci_[mt][0]));
                a[mt][3] = cvt_tf32(Xs[(kb + tg + 4) * 136 + m0 + g + 8] * (f1 * ci_[mt][1]));
            }
            #pragma unroll
            for (int nt = 0; nt < 8; nt++) {
                uint32_t bh[2];
                bh[0] = cvt_tf32(Cs[(kb + tg) * 136 + nb + nt * 8 + g]);
                bh[1] = cvt_tf32(Cs[(kb + tg + 4) * 136 + nb + nt * 8 + g]);
                mma8(acc[0][nt], a[0], bh);
                mma8(acc[1][nt], a[1], bh);
            }
        }
        __syncthreads();
    }

    float* Vp = g_V2p + (size_t)(b * 4 + gc) * LQ * DD;
    #pragma unroll
    for (int mt = 0; mt < 2; mt++) {
        int r0 = mb0 + mt * 16 + g;
        #pragma unroll
        for (int nt = 0; nt < 8; nt++) {
            int d = nb + nt * 8 + 2 * tg;
            *(float2*)(Vp + (size_t)r0 * DD + d)       = make_float2(acc[mt][nt][0], acc[mt][nt][1]);
            *(float2*)(Vp + (size_t)(r0 + 8) * DD + d) = make_float2(acc[mt][nt][2], acc[mt][nt][3]);
        }
    }
}

__global__ __launch_bounds__(256) void v2reduce_kernel() {
    int vec = blockIdx.x * blockDim.x + threadIdx.x;
    const int per_b = LQ * DD / 4;
    if (vec >= BB * per_b) return;
    int b = vec / per_b;
    int off = vec % per_b;
    float4 s = make_float4(0.f, 0.f, 0.f, 0.f);
    #pragma unroll
    for (int g = 0; g < 4; g++) {
        float4 v = ((const float4*)(g_V2p + (size_t)(b * 4 + g) * LQ * DD))[off];
        s.x += v.x; s.y += v.y; s.z += v.z; s.w += v.w;
    }
    ((float4*)g_V2)[vec] = s;
}

// ================= K4: A = P1@Q, Bm = P1@V2 (plain tf32) =================
// Ps holds pre-converted tf32 bits; Bs stages are 32 rows (4 stages/pass).
#define F_DYN ((128 * 130 + 2 * 32 * 136) * 4)
__global__ __launch_bounds__(256, 2) void final_kernel(
    const float* __restrict__ Cg, const float* __restrict__ Qg,
    const int* __restrict__ Qmask, float* __restrict__ out) {
    extern __shared__ float dynf[];
    float* Ps = dynf;                 // [128][130] tf32-bit values
    float* Bsb[2] = {dynf + 128 * 130, dynf + 128 * 130 + 32 * 136};
    int bx = blockIdx.x;
    int b = bx >> 3, i0 = (bx & 7) << 7;
    int t = threadIdx.x, wid = t >> 5, lane = t & 31;
    int g = lane >> 2, tg = lane & 3;
    int wm_ = wid & 3, wn = wid >> 2;
    int mb = wm_ << 5, nb = wn << 6;
    uint32_t bB[2];
    bB[0] = (uint32_t)__cvta_generic_to_shared(Bsb[0]);
    bB[1] = (uint32_t)__cvta_generic_to_shared(Bsb[1]);

    {   // build P1 tile, pre-converted to tf32 bits
        int i = t >> 1, j0 = (t & 1) << 6;
        int gi = b * LC + i0 + i;
        float ri = __ldg(&g_rinv[gi]);
        const float* srow = g_S + (size_t)gi * LQ + j0;
        const int* qm = Qmask + b * LQ + j0;
        float* pr = Ps + i * 130 + j0;
        #pragma unroll
        for (int u = 0; u < 64; u += 4) {
            float4 v = *(const float4*)(srow + u);
            int4 m = *(const int4*)(qm + u);
            pr[u]     = __uint_as_float(cvt_tf32(m.x ? v.x * ri : 0.f));
            pr[u + 1] = __uint_as_float(cvt_tf32(m.y ? v.y * ri : 0.f));
            pr[u + 2] = __uint_as_float(cvt_tf32(m.z ? v.z * ri : 0.f));
            pr[u + 3] = __uint_as_float(cvt_tf32(m.w ? v.w * ri : 0.f));
        }
    }
    __syncthreads();

    // 32-row stages: 1024 16B-chunks / 256 thr = 4 per thread
    #define F_ISSUE(buf, src, kk) {                                         \
        _Pragma("unroll")                                                   \
        for (int u = 0; u < 4; u++) {                                       \
            int gid = u * 256 + t, row = gid >> 5, ch2 = gid & 31;          \
            cpa16(bB[buf] + (row * 136 + ch2 * 4) * 4, (src) + (size_t)((kk) + row) * DD + ch2 * 4); \
        }                                                                   \
        CP_COMMIT(); }

    #pragma unroll
    for (int pass = 0; pass < 2; pass++) {
        const float* Bsrc = pass ? (g_V2 + (size_t)b * LQ * DD) : (Qg + (size_t)b * LQ * DD);
        float acc[2][8][4];
        #pragma unroll
        for (int mt = 0; mt < 2; mt++)
            #pragma unroll
            for (int nt = 0; nt < 8; nt++)
                #pragma unroll
                for (int e = 0; e < 4; e++) acc[mt][nt][e] = 0.f;

        F_ISSUE(0, Bsrc, 0)
        #pragma unroll
        for (int s = 0; s < 4; s++) {
            if (s < 3) F_ISSUE((s + 1) & 1, Bsrc, (s + 1) * 32)
            if (s < 3) { CP_WAIT(1); } else { CP_WAIT(0); }
            __syncthreads();
            const float* Bs = Bsb[s & 1];
            int kk = s * 32;
            #pragma unroll
            for (int k8 = 0; k8 < 4; k8++) {
                int kb = k8 << 3;
                uint32_t a[2][4];
                #pragma unroll
                for (int mt = 0; mt < 2; mt++) {
                    int m0 = mb + mt * 16;
                    a[mt][0] = __float_as_uint(Ps[(m0 + g) * 130 + kk + kb + tg]);
                    a[mt][1] = __float_as_uint(Ps[(m0 + g + 8) * 130 + kk + kb + tg]);
                    a[mt][2] = __float_as_uint(Ps[(m0 + g) * 130 + kk + kb + tg + 4]);
                    a[mt][3] = __float_as_uint(Ps[(m0 + g + 8) * 130 + kk + kb + tg + 4]);
                }
                #pragma unroll
                for (int nt = 0; nt < 8; nt++) {
                    uint32_t bh[2];
                    bh[0] = cvt_tf32(Bs[(kb + tg) * 136 + nb + nt * 8 + g]);
                    bh[1] = cvt_tf32(Bs[(kb + tg + 4) * 136 + nb + nt * 8 + g]);
                    mma8(acc[0][nt], a[0], bh);
                    mma8(acc[1][nt], a[1], bh);
                }
            }
            __syncthreads();
        }

        // epilogue
        #pragma unroll
        for (int mt = 0; mt < 2; mt++) {
            int r0 = i0 + mb + mt * 16 + g, r1 = r0 + 8;
            const float* c0p = Cg + ((size_t)(b * LC + r0)) * DD;
            const float* c1p = Cg + ((size_t)(b * LC + r1)) * DD;
            float* o0 = out + ((size_t)(b * LC + r0)) * (4 * DD);
            float* o1 = out + ((size_t)(b * LC + r1)) * (4 * DD);
            #pragma unroll
            for (int nt = 0; nt < 8; nt++) {
                int d = nb + nt * 8 + 2 * tg;
                float2 c0 = *(const float2*)(c0p + d);
                float2 c1 = *(const float2*)(c1p + d);
                float* a = acc[mt][nt];
                if (pass == 0) {
                    *(float2*)(o0 + d) = c0;
                    *(float2*)(o1 + d) = c1;
                    *(float2*)(o0 + DD + d) = make_float2(a[0], a[1]);
                    *(float2*)(o1 + DD + d) = make_float2(a[2], a[3]);
                    *(float2*)(o0 + 2 * DD + d) = make_float2(c0.x * a[0], c0.y * a[1]);
                    *(float2*)(o1 + 2 * DD + d) = make_float2(c1.x * a[2], c1.y * a[3]);
                } else {
                    *(float2*)(o0 + 3 * DD + d) = make_float2(c0.x * a[0], c0.y * a[1]);
                    *(float2*)(o1 + 3 * DD + d) = make_float2(c1.x * a[2], c1.y * a[3]);
                }
            }
        }
    }
}

// ---------------- launch ----------------
extern "C" void kernel_launch(void* const* d_in, const int* in_sizes, int n_in,
                              void* d_out, int out_size) {
    const float* C     = (const float*)d_in[0];
    const float* Q     = (const float*)d_in[1];
    const int*   Cmask = (const int*)d_in[2];
    const int*   Qmask = (const int*)d_in[3];
    const float* w_c   = (const float*)d_in[4];
    const float* w_q   = (const float*)d_in[5];
    const float* w_mul = (const float*)d_in[6];
    const float* bias  = (const float*)d_in[7];
    float* out = (float*)d_out;

    cudaFuncSetAttribute(s_kernel, cudaFuncAttributeMaxDynamicSharedMemorySize, S_DYN);
    cudaFuncSetAttribute(v2_kernel, cudaFuncAttributeMaxDynamicSharedMemorySize, V2_DYN);
    cudaFuncSetAttribute(final_kernel, cudaFuncAttributeMaxDynamicSharedMemorySize, F_DYN);

    s_kernel<<<BB * 8, 256, S_DYN>>>(C, Q, w_mul, w_c, w_q, bias, Qmask, Cmask);
    colmerge_kernel<<<(BB * LQ + 255) / 256, 256>>>();
    v2_kernel<<<BB * 4, 256, V2_DYN>>>(C, Cmask);
    v2reduce_kernel<<<(BB * LQ * DD / 4 + 255) / 256, 256>>>();
    final_kernel<<<BB * 8, 256, F_DYN>>>(C, Q, Qmask, out);
}

// round 16
// speedup vs baseline: 1.1138x; 1.1138x over previous
#include <cuda_runtime.h>
#include <math.h>
#include <stdint.h>

#define BB 64
#define LC 1024
#define LQ 128
#define DD 128
#define NEG (-1e9f)

// ---------------- device scratch ----------------
__device__ float g_S[(size_t)BB * LC * LQ];      // X = exp(S), 32 MB
__device__ float g_rinv[BB * LC];
__device__ float g_cps[BB * 8 * LQ];
__device__ float g_cinv[BB * LQ];
__device__ float g_V2p[(size_t)4 * BB * LQ * DD];
__device__ float g_V2[BB * LQ * DD];

// ---------------- helpers ----------------
__device__ __forceinline__ void split_tf32(float x, uint32_t& hi, uint32_t& lo) {
    asm("cvt.rna.tf32.f32 %0, %1;" : "=r"(hi) : "f"(x));
    float r = x - __uint_as_float(hi);
    asm("cvt.rna.tf32.f32 %0, %1;" : "=r"(lo) : "f"(r));
}
__device__ __forceinline__ uint32_t cvt_tf32(float x) {
    uint32_t h;
    asm("cvt.rna.tf32.f32 %0, %1;" : "=r"(h) : "f"(x));
    return h;
}
__device__ __forceinline__ void mma8(float* d, const uint32_t* a, const uint32_t* b) {
    asm("mma.sync.aligned.m16n8k8.row.col.f32.tf32.tf32.f32 "
        "{%0,%1,%2,%3}, {%4,%5,%6,%7}, {%8,%9}, {%0,%1,%2,%3};"
        : "+f"(d[0]), "+f"(d[1]), "+f"(d[2]), "+f"(d[3])
        : "r"(a[0]), "r"(a[1]), "r"(a[2]), "r"(a[3]), "r"(b[0]), "r"(b[1]));
}
__device__ __forceinline__ void cpa16(uint32_t dst, const float* src) {
    asm volatile("cp.async.cg.shared.global [%0], [%1], 16;" :: "r"(dst), "l"(src));
}
#define CP_COMMIT() asm volatile("cp.async.commit_group;" ::: "memory")
#define CP_WAIT(n)  asm volatile("cp.async.wait_group %0;" :: "n"(n) : "memory")

// ================= K1: S GEMM (2-term tf32, cp.async) + dots + stats =====
#define S_DYN (4 * 128 * 36 * 4)
__global__ __launch_bounds__(256, 2) void s_kernel(
    const float* __restrict__ Cg, const float* __restrict__ Qg,
    const float* __restrict__ w_mul, const float* __restrict__ w_c,
    const float* __restrict__ w_q, const float* __restrict__ bias,
    const int* __restrict__ Qmask, const int* __restrict__ Cmask) {
    extern __shared__ float dynf[];
    float* Ab[2] = {dynf, dynf + 128 * 36};
    float* Qb2[2] = {dynf + 2 * 128 * 36, dynf + 3 * 128 * 36};
    float* Ss = dynf;                // [128][132] epilogue alias
    __shared__ float s_cd[128], s_qd[128], s_wm[128], s_wc[128], s_wq[128];
    __shared__ float s_s2[128];
    __shared__ int s_qm[128], s_cm[128];

    int bx = blockIdx.x;
    int b = bx >> 3, tile = bx & 7, i0 = tile << 7;
    int t = threadIdx.x, wid = t >> 5, lane = t & 31;
    int g = lane >> 2, tg = lane & 3;
    int wm_ = wid & 3, wn = wid >> 2;
    int mb = wm_ << 5;
    int jb = wn << 6;

    if (t < 128) {
        s_qm[t] = Qmask[b * LQ + t];
        s_cm[t] = Cmask[b * LC + i0 + t];
        s_wm[t] = w_mul[t];
        s_wc[t] = w_c[t];
        s_wq[t] = w_q[t];
    }

    const float* Cb = Cg + ((size_t)b * LC + i0) * DD;
    const float* Qb = Qg + (size_t)b * LQ * DD;
    uint32_t aB[2], qB[2];
    aB[0] = (uint32_t)__cvta_generic_to_shared(Ab[0]);
    aB[1] = (uint32_t)__cvta_generic_to_shared(Ab[1]);
    qB[0] = (uint32_t)__cvta_generic_to_shared(Qb2[0]);
    qB[1] = (uint32_t)__cvta_generic_to_shared(Qb2[1]);

    float acc[2][8][4];
    #pragma unroll
    for (int mt = 0; mt < 2; mt++)
        #pragma unroll
        for (int nt = 0; nt < 8; nt++)
            #pragma unroll
            for (int e = 0; e < 4; e++) acc[mt][nt][e] = 0.f;

    int row0 = t >> 3, ch = t & 7;
    float cdp[4] = {0.f, 0.f, 0.f, 0.f};
    float qdp[4] = {0.f, 0.f, 0.f, 0.f};

    #define S_ISSUE(buf, kk) {                                              \
        _Pragma("unroll")                                                   \
        for (int u = 0; u < 4; u++) {                                       \
            int row = row0 + u * 32;                                        \
            cpa16(aB[buf] + (row * 36 + ch * 4) * 4, Cb + (size_t)row * DD + (kk) + ch * 4); \
            cpa16(qB[buf] + (row * 36 + ch * 4) * 4, Qb + (size_t)row * DD + (kk) + ch * 4); \
        }                                                                   \
        CP_COMMIT(); }

    S_ISSUE(0, 0)
    #pragma unroll
    for (int s = 0; s < 4; s++) {
        if (s < 3) S_ISSUE((s + 1) & 1, (s + 1) * 32)
        if (s < 3) { CP_WAIT(1); } else { CP_WAIT(0); }
        __syncthreads();
        const float* As = Ab[s & 1];
        const float* Qs = Qb2[s & 1];
        int kk = s * 32;
        {   // fused dots partials
            float4 wc = *(const float4*)&s_wc[kk + ch * 4];
            float4 wq = *(const float4*)&s_wq[kk + ch * 4];
            #pragma unroll
            for (int u = 0; u < 4; u++) {
                int row = row0 + u * 32;
                float4 a = *(const float4*)&As[row * 36 + ch * 4];
                cdp[u] += a.x * wc.x + a.y * wc.y + a.z * wc.z + a.w * wc.w;
                float4 q = *(const float4*)&Qs[row * 36 + ch * 4];
                qdp[u] += q.x * wq.x + q.y * wq.y + q.z * wq.z + q.w * wq.w;
            }
        }
        #pragma unroll
        for (int k8 = 0; k8 < 4; k8++) {
            int kb = k8 << 3;
            float wm0 = s_wm[kk + kb + tg], wm1 = s_wm[kk + kb + tg + 4];
            uint32_t ah[2][4], al[2][4];
            #pragma unroll
            for (int mt = 0; mt < 2; mt++) {
                int m0 = mb + mt * 16;
                split_tf32(As[(m0 + g) * 36 + kb + tg] * wm0,         ah[mt][0], al[mt][0]);
                split_tf32(As[(m0 + g + 8) * 36 + kb + tg] * wm0,     ah[mt][1], al[mt][1]);
                split_tf32(As[(m0 + g) * 36 + kb + tg + 4] * wm1,     ah[mt][2], al[mt][2]);
                split_tf32(As[(m0 + g + 8) * 36 + kb + tg + 4] * wm1, ah[mt][3], al[mt][3]);
            }
            #pragma unroll
            for (int nt = 0; nt < 8; nt++) {
                uint32_t bh[2];
                bh[0] = cvt_tf32(Qs[(jb + nt * 8 + g) * 36 + kb + tg]);
                bh[1] = cvt_tf32(Qs[(jb + nt * 8 + g) * 36 + kb + tg + 4]);
                mma8(acc[0][nt], ah[0], bh);
                mma8(acc[0][nt], al[0], bh);
                mma8(acc[1][nt], ah[1], bh);
                mma8(acc[1][nt], al[1], bh);
            }
        }
        __syncthreads();
    }

    // reduce dots over the 8 threads sharing a row
    #pragma unroll
    for (int u = 0; u < 4; u++) {
        #pragma unroll
        for (int o = 1; o < 8; o <<= 1) {
            cdp[u] += __shfl_xor_sync(0xffffffffu, cdp[u], o);
            qdp[u] += __shfl_xor_sync(0xffffffffu, qdp[u], o);
        }
        if (ch == 0) {
            s_cd[row0 + u * 32] = cdp[u];
            s_qd[row0 + u * 32] = qdp[u];
        }
    }
    __syncthreads();

    // finalize S into Ss
    {
        float bi = bias[0];
        #pragma unroll
        for (int mt = 0; mt < 2; mt++) {
            int m0 = mb + mt * 16;
            float cd0 = s_cd[m0 + g] + bi, cd1 = s_cd[m0 + g + 8] + bi;
            #pragma unroll
            for (int nt = 0; nt < 8; nt++) {
                int c0 = jb + nt * 8 + 2 * tg;
                float q0 = s_qd[c0], q1 = s_qd[c0 + 1];
                Ss[(m0 + g) * 132 + c0]     = acc[mt][nt][0] + cd0 + q0;
                Ss[(m0 + g) * 132 + c0 + 1] = acc[mt][nt][1] + cd0 + q1;
                Ss[(m0 + g + 8) * 132 + c0]     = acc[mt][nt][2] + cd1 + q0;
                Ss[(m0 + g + 8) * 132 + c0 + 1] = acc[mt][nt][3] + cd1 + q1;
            }
        }
    }
    __syncthreads();

    // phase A: X = exp(S) -> Ss & g_S ; masked row sums
    {
        int i = t >> 1, j0 = (t & 1) << 6;
        float sm = 0.f;
        float* dst = g_S + ((size_t)(b * LC + i0 + i)) * LQ + j0;
        #pragma unroll
        for (int u = 0; u < 64; u += 4) {
            float4 v = *(const float4*)&Ss[i * 132 + j0 + u];
            int4 m = *(const int4*)&s_qm[j0 + u];
            float4 x = make_float4(__expf(v.x), __expf(v.y), __expf(v.z), __expf(v.w));
            *(float4*)&Ss[i * 132 + j0 + u] = x;
            *(float4*)(dst + u) = x;
            sm += (m.x ? x.x : 0.f) + (m.y ? x.y : 0.f)
                + (m.z ? x.z : 0.f) + (m.w ? x.w : 0.f);
        }
        sm += __shfl_xor_sync(0xffffffffu, sm, 1);
        if ((t & 1) == 0) g_rinv[b * LC + i0 + i] = 1.f / sm;
    }
    __syncthreads();

    // phase B: masked column partial sums
    {
        int j = t & 127, ih = t >> 7;
        float s = 0.f;
        #pragma unroll 8
        for (int r = 0; r < 64; r++) {
            int i = ih * 64 + r;
            s += s_cm[i] ? Ss[i * 132 + j] : 0.f;
        }
        if (ih == 1) s_s2[j] = s;
        __syncthreads();
        if (ih == 0)
            g_cps[(b * 8 + tile) * LQ + j] = s + s_s2[j];
    }
}

// ================= K2: merge column partial sums =================
__global__ __launch_bounds__(256) void colmerge_kernel() {
    int idx = blockIdx.x * blockDim.x + threadIdx.x;
    if (idx >= BB * LQ) return;
    int b = idx >> 7, j = idx & 127;
    float S = 0.f;
    #pragma unroll
    for (int g = 0; g < 8; g++) S += g_cps[(b * 8 + g) * LQ + j];
    g_cinv[idx] = 1.f / S;
}

// ================= K3: V2 partial (plain tf32, cp.async), split-K=4 ======
#define V2_DYN (4 * 32 * 136 * 4)
__global__ __launch_bounds__(256, 2) void v2_kernel(
    const float* __restrict__ Cg, const int* __restrict__ Cmask) {
    extern __shared__ float dynf[];
    float* Xb[2] = {dynf, dynf + 32 * 136};
    float* Cb2[2] = {dynf + 2 * 32 * 136, dynf + 3 * 32 * 136};
    __shared__ int s_cm[256];
    int b = blockIdx.x >> 2, gc = blockIdx.x & 3;
    int t = threadIdx.x, wid = t >> 5, lane = t & 31;
    int g = lane >> 2, tg = lane & 3;
    int wm_ = wid >> 1, wn = wid & 1;
    int mb0 = wm_ << 5;
    int nb = wn << 6;
    s_cm[t] = Cmask[b * LC + gc * 256 + t];

    float ci_[2][2];
    #pragma unroll
    for (int mt = 0; mt < 2; mt++) {
        ci_[mt][0] = g_cinv[b * LQ + mb0 + mt * 16 + g];
        ci_[mt][1] = g_cinv[b * LQ + mb0 + mt * 16 + g + 8];
    }

    const float* Sb = g_S + ((size_t)(b * LC + gc * 256)) * LQ;
    const float* Cb = Cg + ((size_t)(b * LC + gc * 256)) * DD;
    uint32_t xB[2], cB[2];
    xB[0] = (uint32_t)__cvta_generic_to_shared(Xb[0]);
    xB[1] = (uint32_t)__cvta_generic_to_shared(Xb[1]);
    cB[0] = (uint32_t)__cvta_generic_to_shared(Cb2[0]);
    cB[1] = (uint32_t)__cvta_generic_to_shared(Cb2[1]);

    float acc[2][8][4];
    #pragma unroll
    for (int mt = 0; mt < 2; mt++)
        #pragma unroll
        for (int nt = 0; nt < 8; nt++)
            #pragma unroll
            for (int e = 0; e < 4; e++) acc[mt][nt][e] = 0.f;

    #define V_ISSUE(buf, ik) {                                              \
        _Pragma("unroll")                                                   \
        for (int u = 0; u < 4; u++) {                                       \
            int gid = u * 256 + t, row = gid >> 5, ch = gid & 31;           \
            cpa16(xB[buf] + (row * 136 + ch * 4) * 4, Sb + (size_t)((ik) + row) * LQ + ch * 4); \
            cpa16(cB[buf] + (row * 136 + ch * 4) * 4, Cb + (size_t)((ik) + row) * DD + ch * 4); \
        }                                                                   \
        CP_COMMIT(); }

    V_ISSUE(0, 0)
    #pragma unroll
    for (int s = 0; s < 8; s++) {
        if (s < 7) V_ISSUE((s + 1) & 1, (s + 1) * 32)
        if (s < 7) { CP_WAIT(1); } else { CP_WAIT(0); }
        __syncthreads();
        const float* Xs = Xb[s & 1];
        const float* Cs = Cb2[s & 1];
        int ik = s * 32;
        #pragma unroll
        for (int k8 = 0; k8 < 4; k8++) {
            int kb = k8 << 3;
            float f0 = s_cm[ik + kb + tg] ? 1.f : 0.f;
            float f1 = s_cm[ik + kb + tg + 4] ? 1.f : 0.f;
            uint32_t a[2][4];
            #pragma unroll
            for (int mt = 0; mt < 2; mt++) {
                int m0 = mb0 + mt * 16;
                a[mt][0] = cvt_tf32(Xs[(kb + tg) * 136 + m0 + g] * (f0 * ci_[mt][0]));
                a[mt][1] = cvt_tf32(Xs[(kb + tg) * 136 + m0 + g + 8] * (f0 * ci_[mt][1]));
                a[mt][2] = cvt_tf32(Xs[(kb + tg + 4) * 136 + m0 + g] * (f1 * ci_[mt][0]));
                a[mt][3] = cvt_tf32(Xs[(kb + tg + 4) * 136 + m0 + g + 8] * (f1 * ci_[mt][1]));
            }
            #pragma unroll
            for (int nt = 0; nt < 8; nt++) {
                uint32_t bh[2];
                bh[0] = cvt_tf32(Cs[(kb + tg) * 136 + nb + nt * 8 + g]);
                bh[1] = cvt_tf32(Cs[(kb + tg + 4) * 136 + nb + nt * 8 + g]);
                mma8(acc[0][nt], a[0], bh);
                mma8(acc[1][nt], a[1], bh);
            }
        }
        __syncthreads();
    }

    float* Vp = g_V2p + (size_t)(b * 4 + gc) * LQ * DD;
    #pragma unroll
    for (int mt = 0; mt < 2; mt++) {
        int r0 = mb0 + mt * 16 + g;
        #pragma unroll
        for (int nt = 0; nt < 8; nt++) {
            int d = nb + nt * 8 + 2 * tg;
            *(float2*)(Vp + (size_t)r0 * DD + d)       = make_float2(acc[mt][nt][0], acc[mt][nt][1]);
            *(float2*)(Vp + (size_t)(r0 + 8) * DD + d) = make_float2(acc[mt][nt][2], acc[mt][nt][3]);
        }
    }
}

__global__ __launch_bounds__(256) void v2reduce_kernel() {
    int vec = blockIdx.x * blockDim.x + threadIdx.x;
    const int per_b = LQ * DD / 4;
    if (vec >= BB * per_b) return;
    int b = vec / per_b;
    int off = vec % per_b;
    float4 s = make_float4(0.f, 0.f, 0.f, 0.f);
    #pragma unroll
    for (int g = 0; g < 4; g++) {
        float4 v = ((const float4*)(g_V2p + (size_t)(b * 4 + g) * LQ * DD))[off];
        s.x += v.x; s.y += v.y; s.z += v.z; s.w += v.w;
    }
    ((float4*)g_V2)[vec] = s;
}

// ================= K4: A = P1@Q, Bm = P1@V2 (plain tf32, cp.async Bs) ====
#define F_DYN ((128 * 130 + 2 * 16 * 136) * 4)
__global__ __launch_bounds__(256, 2) void final_kernel(
    const float* __restrict__ Cg, const float* __restrict__ Qg,
    const int* __restrict__ Qmask, float* __restrict__ out) {
    extern __shared__ float dynf[];
    float* Ps = dynf;                 // [128][130]
    float* Bsb[2] = {dynf + 128 * 130, dynf + 128 * 130 + 16 * 136};
    int bx = blockIdx.x;
    int b = bx >> 3, i0 = (bx & 7) << 7;
    int t = threadIdx.x, wid = t >> 5, lane = t & 31;
    int g = lane >> 2, tg = lane & 3;
    int wm_ = wid & 3, wn = wid >> 2;
    int mb = wm_ << 5, nb = wn << 6;
    uint32_t bB[2];
    bB[0] = (uint32_t)__cvta_generic_to_shared(Bsb[0]);
    bB[1] = (uint32_t)__cvta_generic_to_shared(Bsb[1]);

    {   // build P1 tile (no exp)
        int i = t >> 1, j0 = (t & 1) << 6;
        int gi = b * LC + i0 + i;
        float ri = __ldg(&g_rinv[gi]);
        const float* srow = g_S + (size_t)gi * LQ + j0;
        const int* qm = Qmask + b * LQ + j0;
        float* pr = Ps + i * 130 + j0;
        #pragma unroll
        for (int u = 0; u < 64; u += 4) {
            float4 v = *(const float4*)(srow + u);
            int4 m = *(const int4*)(qm + u);
            pr[u]     = m.x ? v.x * ri : 0.f;
            pr[u + 1] = m.y ? v.y * ri : 0.f;
            pr[u + 2] = m.z ? v.z * ri : 0.f;
            pr[u + 3] = m.w ? v.w * ri : 0.f;
        }
    }
    __syncthreads();

    #define F_ISSUE(buf, src, kk) {                                         \
        _Pragma("unroll")                                                   \
        for (int u = 0; u < 2; u++) {                                       \
            int gid = u * 256 + t, row = gid >> 5, ch2 = gid & 31;          \
            cpa16(bB[buf] + (row * 136 + ch2 * 4) * 4, (src) + (size_t)((kk) + row) * DD + ch2 * 4); \
        }                                                                   \
        CP_COMMIT(); }

    #pragma unroll
    for (int pass = 0; pass < 2; pass++) {
        const float* Bsrc = pass ? (g_V2 + (size_t)b * LQ * DD) : (Qg + (size_t)b * LQ * DD);
        float acc[2][8][4];
        #pragma unroll
        for (int mt = 0; mt < 2; mt++)
            #pragma unroll
            for (int nt = 0; nt < 8; nt++)
                #pragma unroll
                for (int e = 0; e < 4; e++) acc[mt][nt][e] = 0.f;

        F_ISSUE(0, Bsrc, 0)
        #pragma unroll
        for (int s = 0; s < 8; s++) {
            if (s < 7) F_ISSUE((s + 1) & 1, Bsrc, (s + 1) * 16)
            if (s < 7) { CP_WAIT(1); } else { CP_WAIT(0); }
            __syncthreads();
            const float* Bs = Bsb[s & 1];
            int kk = s * 16;
            #pragma unroll
            for (int k8 = 0; k8 < 2; k8++) {
                int kb = k8 << 3;
                uint32_t a[2][4];
                #pragma unroll
                for (int mt = 0; mt < 2; mt++) {
                    int m0 = mb + mt * 16;
                    a[mt][0] = cvt_tf32(Ps[(m0 + g) * 130 + kk + kb + tg]);
                    a[mt][1] = cvt_tf32(Ps[(m0 + g + 8) * 130 + kk + kb + tg]);
                    a[mt][2] = cvt_tf32(Ps[(m0 + g) * 130 + kk + kb + tg + 4]);
                    a[mt][3] = cvt_tf32(Ps[(m0 + g + 8) * 130 + kk + kb + tg + 4]);
                }
                #pragma unroll
                for (int nt = 0; nt < 8; nt++) {
                    uint32_t bh[2];
                    bh[0] = cvt_tf32(Bs[(kb + tg) * 136 + nb + nt * 8 + g]);
                    bh[1] = cvt_tf32(Bs[(kb + tg + 4) * 136 + nb + nt * 8 + g]);
                    mma8(acc[0][nt], a[0], bh);
                    mma8(acc[1][nt], a[1], bh);
                }
            }
            __syncthreads();
        }

        // epilogue
        #pragma unroll
        for (int mt = 0; mt < 2; mt++) {
            int r0 = i0 + mb + mt * 16 + g, r1 = r0 + 8;
            const float* c0p = Cg + ((size_t)(b * LC + r0)) * DD;
            const float* c1p = Cg + ((size_t)(b * LC + r1)) * DD;
            float* o0 = out + ((size_t)(b * LC + r0)) * (4 * DD);
            float* o1 = out + ((size_t)(b * LC + r1)) * (4 * DD);
            #pragma unroll
            for (int nt = 0; nt < 8; nt++) {
                int d = nb + nt * 8 + 2 * tg;
                float2 c0 = *(const float2*)(c0p + d);
                float2 c1 = *(const float2*)(c1p + d);
                float* a = acc[mt][nt];
                if (pass == 0) {
                    *(float2*)(o0 + d) = c0;
                    *(float2*)(o1 + d) = c1;
                    *(float2*)(o0 + DD + d) = make_float2(a[0], a[1]);
                    *(float2*)(o1 + DD + d) = make_float2(a[2], a[3]);
                    *(float2*)(o0 + 2 * DD + d) = make_float2(c0.x * a[0], c0.y * a[1]);
                    *(float2*)(o1 + 2 * DD + d) = make_float2(c1.x * a[2], c1.y * a[3]);
                } else {
                    *(float2*)(o0 + 3 * DD + d) = make_float2(c0.x * a[0], c0.y * a[1]);
                    *(float2*)(o1 + 3 * DD + d) = make_float2(c1.x * a[2], c1.y * a[3]);
                }
            }
        }
    }
}

// ---------------- launch ----------------
extern "C" void kernel_launch(void* const* d_in, const int* in_sizes, int n_in,
                              void* d_out, int out_size) {
    const float* C     = (const float*)d_in[0];
    const float* Q     = (const float*)d_in[1];
    const int*   Cmask = (const int*)d_in[2];
    const int*   Qmask = (const int*)d_in[3];
    const float* w_c   = (const float*)d_in[4];
    const float* w_q   = (const float*)d_in[5];
    const float* w_mul = (const float*)d_in[6];
    const float* bias  = (const float*)d_in[7];
    float* out = (float*)d_out;

    cudaFuncSetAttribute(s_kernel, cudaFuncAttributeMaxDynamicSharedMemorySize, S_DYN);
    cudaFuncSetAttribute(v2_kernel, cudaFuncAttributeMaxDynamicSharedMemorySize, V2_DYN);
    cudaFuncSetAttribute(final_kernel, cudaFuncAttributeMaxDynamicSharedMemorySize, F_DYN);

    s_kernel<<<BB * 8, 256, S_DYN>>>(C, Q, w_mul, w_c, w_q, bias, Qmask, Cmask);
    colmerge_kernel<<<(BB * LQ + 255) / 256, 256>>>();
    v2_kernel<<<BB * 4, 256, V2_DYN>>>(C, Cmask);
    v2reduce_kernel<<<(BB * LQ * DD / 4 + 255) / 256, 256>>>();
    final_kernel<<<BB * 8, 256, F_DYN>>>(C, Q, Qmask, out);
}

// round 17
// speedup vs baseline: 1.1701x; 1.0505x over previous
#include <cuda_runtime.h>
#include <math.h>
#include <stdint.h>

#define BB 64
#define LC 1024
#define LQ 128
#define DD 128
#define NEG (-1e9f)

// ---------------- device scratch ----------------
__device__ float g_S[(size_t)BB * LC * LQ];      // X = exp(S), 32 MB
__device__ float g_rinv[BB * LC];
__device__ float g_cps[BB * 8 * LQ];
__device__ float g_cinv[BB * LQ];
__device__ float g_V2p[(size_t)4 * BB * LQ * DD];
__device__ float g_V2[BB * LQ * DD];

// ---------------- helpers ----------------
__device__ __forceinline__ uint32_t cvt_tf32(float x) {
    uint32_t h;
    asm("cvt.rna.tf32.f32 %0, %1;" : "=r"(h) : "f"(x));
    return h;
}
__device__ __forceinline__ void mma8(float* d, const uint32_t* a, const uint32_t* b) {
    asm("mma.sync.aligned.m16n8k8.row.col.f32.tf32.tf32.f32 "
        "{%0,%1,%2,%3}, {%4,%5,%6,%7}, {%8,%9}, {%0,%1,%2,%3};"
        : "+f"(d[0]), "+f"(d[1]), "+f"(d[2]), "+f"(d[3])
        : "r"(a[0]), "r"(a[1]), "r"(a[2]), "r"(a[3]), "r"(b[0]), "r"(b[1]));
}
__device__ __forceinline__ void cpa16(uint32_t dst, const float* src) {
    asm volatile("cp.async.cg.shared.global [%0], [%1], 16;" :: "r"(dst), "l"(src));
}
#define CP_COMMIT() asm volatile("cp.async.commit_group;" ::: "memory")
#define CP_WAIT(n)  asm volatile("cp.async.wait_group %0;" :: "n"(n) : "memory")

// ================= K1: S GEMM (single tf32, cp.async) + dots + stats =====
#define S_DYN (4 * 128 * 36 * 4)
__global__ __launch_bounds__(256, 2) void s_kernel(
    const float* __restrict__ Cg, const float* __restrict__ Qg,
    const float* __restrict__ w_mul, const float* __restrict__ w_c,
    const float* __restrict__ w_q, const float* __restrict__ bias,
    const int* __restrict__ Qmask, const int* __restrict__ Cmask) {
    extern __shared__ float dynf[];
    float* Ab[2] = {dynf, dynf + 128 * 36};
    float* Qb2[2] = {dynf + 2 * 128 * 36, dynf + 3 * 128 * 36};
    float* Ss = dynf;                // [128][132] epilogue alias
    __shared__ float s_cd[128], s_qd[128], s_wm[128], s_wc[128], s_wq[128];
    __shared__ float s_s2[128];
    __shared__ int s_qm[128], s_cm[128];

    int bx = blockIdx.x;
    int b = bx >> 3, tile = bx & 7, i0 = tile << 7;
    int t = threadIdx.x, wid = t >> 5, lane = t & 31;
    int g = lane >> 2, tg = lane & 3;
    int wm_ = wid & 3, wn = wid >> 2;
    int mb = wm_ << 5;
    int jb = wn << 6;

    if (t < 128) {
        s_qm[t] = Qmask[b * LQ + t];
        s_cm[t] = Cmask[b * LC + i0 + t];
        s_wm[t] = w_mul[t];
        s_wc[t] = w_c[t];
        s_wq[t] = w_q[t];
    }

    const float* Cb = Cg + ((size_t)b * LC + i0) * DD;
    const float* Qb = Qg + (size_t)b * LQ * DD;
    uint32_t aB[2], qB[2];
    aB[0] = (uint32_t)__cvta_generic_to_shared(Ab[0]);
    aB[1] = (uint32_t)__cvta_generic_to_shared(Ab[1]);
    qB[0] = (uint32_t)__cvta_generic_to_shared(Qb2[0]);
    qB[1] = (uint32_t)__cvta_generic_to_shared(Qb2[1]);

    float acc[2][8][4];
    #pragma unroll
    for (int mt = 0; mt < 2; mt++)
        #pragma unroll
        for (int nt = 0; nt < 8; nt++)
            #pragma unroll
            for (int e = 0; e < 4; e++) acc[mt][nt][e] = 0.f;

    int row0 = t >> 3, ch = t & 7;
    float cdp[4] = {0.f, 0.f, 0.f, 0.f};
    float qdp[4] = {0.f, 0.f, 0.f, 0.f};

    #define S_ISSUE(buf, kk) {                                              \
        _Pragma("unroll")                                                   \
        for (int u = 0; u < 4; u++) {                                       \
            int row = row0 + u * 32;                                        \
            cpa16(aB[buf] + (row * 36 + ch * 4) * 4, Cb + (size_t)row * DD + (kk) + ch * 4); \
            cpa16(qB[buf] + (row * 36 + ch * 4) * 4, Qb + (size_t)row * DD + (kk) + ch * 4); \
        }                                                                   \
        CP_COMMIT(); }

    S_ISSUE(0, 0)
    #pragma unroll
    for (int s = 0; s < 4; s++) {
        if (s < 3) S_ISSUE((s + 1) & 1, (s + 1) * 32)
        if (s < 3) { CP_WAIT(1); } else { CP_WAIT(0); }
        __syncthreads();
        const float* As = Ab[s & 1];
        const float* Qs = Qb2[s & 1];
        int kk = s * 32;
        {   // fused dots partials
            float4 wc = *(const float4*)&s_wc[kk + ch * 4];
            float4 wq = *(const float4*)&s_wq[kk + ch * 4];
            #pragma unroll
            for (int u = 0; u < 4; u++) {
                int row = row0 + u * 32;
                float4 a = *(const float4*)&As[row * 36 + ch * 4];
                cdp[u] += a.x * wc.x + a.y * wc.y + a.z * wc.z + a.w * wc.w;
                float4 q = *(const float4*)&Qs[row * 36 + ch * 4];
                qdp[u] += q.x * wq.x + q.y * wq.y + q.z * wq.z + q.w * wq.w;
            }
        }
        #pragma unroll
        for (int k8 = 0; k8 < 4; k8++) {
            int kb = k8 << 3;
            float wm0 = s_wm[kk + kb + tg], wm1 = s_wm[kk + kb + tg + 4];
            uint32_t a[2][4];
            #pragma unroll
            for (int mt = 0; mt < 2; mt++) {
                int m0 = mb + mt * 16;
                a[mt][0] = cvt_tf32(As[(m0 + g) * 36 + kb + tg] * wm0);
                a[mt][1] = cvt_tf32(As[(m0 + g + 8) * 36 + kb + tg] * wm0);
                a[mt][2] = cvt_tf32(As[(m0 + g) * 36 + kb + tg + 4] * wm1);
                a[mt][3] = cvt_tf32(As[(m0 + g + 8) * 36 + kb + tg + 4] * wm1);
            }
            #pragma unroll
            for (int nt = 0; nt < 8; nt++) {
                uint32_t bh[2];
                bh[0] = cvt_tf32(Qs[(jb + nt * 8 + g) * 36 + kb + tg]);
                bh[1] = cvt_tf32(Qs[(jb + nt * 8 + g) * 36 + kb + tg + 4]);
                mma8(acc[0][nt], a[0], bh);
                mma8(acc[1][nt], a[1], bh);
            }
        }
        __syncthreads();
    }

    // reduce dots over the 8 threads sharing a row
    #pragma unroll
    for (int u = 0; u < 4; u++) {
        #pragma unroll
        for (int o = 1; o < 8; o <<= 1) {
            cdp[u] += __shfl_xor_sync(0xffffffffu, cdp[u], o);
            qdp[u] += __shfl_xor_sync(0xffffffffu, qdp[u], o);
        }
        if (ch == 0) {
            s_cd[row0 + u * 32] = cdp[u];
            s_qd[row0 + u * 32] = qdp[u];
        }
    }
    __syncthreads();

    // finalize S into Ss
    {
        float bi = bias[0];
        #pragma unroll
        for (int mt = 0; mt < 2; mt++) {
            int m0 = mb + mt * 16;
            float cd0 = s_cd[m0 + g] + bi, cd1 = s_cd[m0 + g + 8] + bi;
            #pragma unroll
            for (int nt = 0; nt < 8; nt++) {
                int c0 = jb + nt * 8 + 2 * tg;
                float q0 = s_qd[c0], q1 = s_qd[c0 + 1];
                Ss[(m0 + g) * 132 + c0]     = acc[mt][nt][0] + cd0 + q0;
                Ss[(m0 + g) * 132 + c0 + 1] = acc[mt][nt][1] + cd0 + q1;
                Ss[(m0 + g + 8) * 132 + c0]     = acc[mt][nt][2] + cd1 + q0;
                Ss[(m0 + g + 8) * 132 + c0 + 1] = acc[mt][nt][3] + cd1 + q1;
            }
        }
    }
    __syncthreads();

    // phase A: X = exp(S) -> Ss & g_S ; masked row sums
    {
        int i = t >> 1, j0 = (t & 1) << 6;
        float sm = 0.f;
        float* dst = g_S + ((size_t)(b * LC + i0 + i)) * LQ + j0;
        #pragma unroll
        for (int u = 0; u < 64; u += 4) {
            float4 v = *(const float4*)&Ss[i * 132 + j0 + u];
            int4 m = *(const int4*)&s_qm[j0 + u];
            float4 x = make_float4(__expf(v.x), __expf(v.y), __expf(v.z), __expf(v.w));
            *(float4*)&Ss[i * 132 + j0 + u] = x;
            *(float4*)(dst + u) = x;
            sm += (m.x ? x.x : 0.f) + (m.y ? x.y : 0.f)
                + (m.z ? x.z : 0.f) + (m.w ? x.w : 0.f);
        }
        sm += __shfl_xor_sync(0xffffffffu, sm, 1);
        if ((t & 1) == 0) g_rinv[b * LC + i0 + i] = 1.f / sm;
    }
    __syncthreads();

    // phase B: masked column partial sums
    {
        int j = t & 127, ih = t >> 7;
        float s = 0.f;
        #pragma unroll 8
        for (int r = 0; r < 64; r++) {
            int i = ih * 64 + r;
            s += s_cm[i] ? Ss[i * 132 + j] : 0.f;
        }
        if (ih == 1) s_s2[j] = s;
        __syncthreads();
        if (ih == 0)
            g_cps[(b * 8 + tile) * LQ + j] = s + s_s2[j];
    }
}

// ================= K2: merge column partial sums =================
__global__ __launch_bounds__(256) void colmerge_kernel() {
    int idx = blockIdx.x * blockDim.x + threadIdx.x;
    if (idx >= BB * LQ) return;
    int b = idx >> 7, j = idx & 127;
    float S = 0.f;
    #pragma unroll
    for (int g = 0; g < 8; g++) S += g_cps[(b * 8 + g) * LQ + j];
    g_cinv[idx] = 1.f / S;
}

// ================= K3: V2 partial (plain tf32, cp.async), split-K=4 ======
#define V2_DYN (4 * 32 * 136 * 4)
__global__ __launch_bounds__(256, 2) void v2_kernel(
    const float* __restrict__ Cg, const int* __restrict__ Cmask) {
    extern __shared__ float dynf[];
    float* Xb[2] = {dynf, dynf + 32 * 136};
    float* Cb2[2] = {dynf + 2 * 32 * 136, dynf + 3 * 32 * 136};
    __shared__ int s_cm[256];
    int b = blockIdx.x >> 2, gc = blockIdx.x & 3;
    int t = threadIdx.x, wid = t >> 5, lane = t & 31;
    int g = lane >> 2, tg = lane & 3;
    int wm_ = wid >> 1, wn = wid & 1;
    int mb0 = wm_ << 5;
    int nb = wn << 6;
    s_cm[t] = Cmask[b * LC + gc * 256 + t];

    float ci_[2][2];
    #pragma unroll
    for (int mt = 0; mt < 2; mt++) {
        ci_[mt][0] = g_cinv[b * LQ + mb0 + mt * 16 + g];
        ci_[mt][1] = g_cinv[b * LQ + mb0 + mt * 16 + g + 8];
    }

    const float* Sb = g_S + ((size_t)(b * LC + gc * 256)) * LQ;
    const float* Cb = Cg + ((size_t)(b * LC + gc * 256)) * DD;
    uint32_t xB[2], cB[2];
    xB[0] = (uint32_t)__cvta_generic_to_shared(Xb[0]);
    xB[1] = (uint32_t)__cvta_generic_to_shared(Xb[1]);
    cB[0] = (uint32_t)__cvta_generic_to_shared(Cb2[0]);
    cB[1] = (uint32_t)__cvta_generic_to_shared(Cb2[1]);

    float acc[2][8][4];
    #pragma unroll
    for (int mt = 0; mt < 2; mt++)
        #pragma unroll
        for (int nt = 0; nt < 8; nt++)
            #pragma unroll
            for (int e = 0; e < 4; e++) acc[mt][nt][e] = 0.f;

    #define V_ISSUE(buf, ik) {                                              \
        _Pragma("unroll")                                                   \
        for (int u = 0; u < 4; u++) {                                       \
            int gid = u * 256 + t, row = gid >> 5, ch = gid & 31;           \
            cpa16(xB[buf] + (row * 136 + ch * 4) * 4, Sb + (size_t)((ik) + row) * LQ + ch * 4); \
            cpa16(cB[buf] + (row * 136 + ch * 4) * 4, Cb + (size_t)((ik) + row) * DD + ch * 4); \
        }                                                                   \
        CP_COMMIT(); }

    V_ISSUE(0, 0)
    #pragma unroll
    for (int s = 0; s < 8; s++) {
        if (s < 7) V_ISSUE((s + 1) & 1, (s + 1) * 32)
        if (s < 7) { CP_WAIT(1); } else { CP_WAIT(0); }
        __syncthreads();
        const float* Xs = Xb[s & 1];
        const float* Cs = Cb2[s & 1];
        int ik = s * 32;
        #pragma unroll
        for (int k8 = 0; k8 < 4; k8++) {
            int kb = k8 << 3;
            float f0 = s_cm[ik + kb + tg] ? 1.f : 0.f;
            float f1 = s_cm[ik + kb + tg + 4] ? 1.f : 0.f;
            uint32_t a[2][4];
            #pragma unroll
            for (int mt = 0; mt < 2; mt++) {
                int m0 = mb0 + mt * 16;
                a[mt][0] = cvt_tf32(Xs[(kb + tg) * 136 + m0 + g] * (f0 * ci_[mt][0]));
                a[mt][1] = cvt_tf32(Xs[(kb + tg) * 136 + m0 + g + 8] * (f0 * ci_[mt][1]));
                a[mt][2] = cvt_tf32(Xs[(kb + tg + 4) * 136 + m0 + g] * (f1 * ci_[mt][0]));
                a[mt][3] = cvt_tf32(Xs[(kb + tg + 4) * 136 + m0 + g + 8] * (f1 * ci_[mt][1]));
            }
            #pragma unroll
            for (int nt = 0; nt < 8; nt++) {
                uint32_t bh[2];
                bh[0] = cvt_tf32(Cs[(kb + tg) * 136 + nb + nt * 8 + g]);
                bh[1] = cvt_tf32(Cs[(kb + tg + 4) * 136 + nb + nt * 8 + g]);
                mma8(acc[0][nt], a[0], bh);
                mma8(acc[1][nt], a[1], bh);
            }
        }
        __syncthreads();
    }

    float* Vp = g_V2p + (size_t)(b * 4 + gc) * LQ * DD;
    #pragma unroll
    for (int mt = 0; mt < 2; mt++) {
        int r0 = mb0 + mt * 16 + g;
        #pragma unroll
        for (int nt = 0; nt < 8; nt++) {
            int d = nb + nt * 8 + 2 * tg;
            *(float2*)(Vp + (size_t)r0 * DD + d)       = make_float2(acc[mt][nt][0], acc[mt][nt][1]);
            *(float2*)(Vp + (size_t)(r0 + 8) * DD + d) = make_float2(acc[mt][nt][2], acc[mt][nt][3]);
        }
    }
}

__global__ __launch_bounds__(256) void v2reduce_kernel() {
    int vec = blockIdx.x * blockDim.x + threadIdx.x;
    const int per_b = LQ * DD / 4;
    if (vec >= BB * per_b) return;
    int b = vec / per_b;
    int off = vec % per_b;
    float4 s = make_float4(0.f, 0.f, 0.f, 0.f);
    #pragma unroll
    for (int g = 0; g < 4; g++) {
        float4 v = ((const float4*)(g_V2p + (size_t)(b * 4 + g) * LQ * DD))[off];
        s.x += v.x; s.y += v.y; s.z += v.z; s.w += v.w;
    }
    ((float4*)g_V2)[vec] = s;
}

// ================= K4: A = P1@Q, Bm = P1@V2 (plain tf32, cp.async Bs) ====
#define F_DYN ((128 * 130 + 2 * 16 * 136) * 4)
__global__ __launch_bounds__(256, 2) void final_kernel(
    const float* __restrict__ Cg, const float* __restrict__ Qg,
    const int* __restrict__ Qmask, float* __restrict__ out) {
    extern __shared__ float dynf[];
    float* Ps = dynf;                 // [128][130]
    float* Bsb[2] = {dynf + 128 * 130, dynf + 128 * 130 + 16 * 136};
    int bx = blockIdx.x;
    int b = bx >> 3, i0 = (bx & 7) << 7;
    int t = threadIdx.x, wid = t >> 5, lane = t & 31;
    int g = lane >> 2, tg = lane & 3;
    int wm_ = wid & 3, wn = wid >> 2;
    int mb = wm_ << 5, nb = wn << 6;
    uint32_t bB[2];
    bB[0] = (uint32_t)__cvta_generic_to_shared(Bsb[0]);
    bB[1] = (uint32_t)__cvta_generic_to_shared(Bsb[1]);

    {   // build P1 tile (no exp)
        int i = t >> 1, j0 = (t & 1) << 6;
        int gi = b * LC + i0 + i;
        float ri = __ldg(&g_rinv[gi]);
        const float* srow = g_S + (size_t)gi * LQ + j0;
        const int* qm = Qmask + b * LQ + j0;
        float* pr = Ps + i * 130 + j0;
        #pragma unroll
        for (int u = 0; u < 64; u += 4) {
            float4 v = *(const float4*)(srow + u);
            int4 m = *(const int4*)(qm + u);
            pr[u]     = m.x ? v.x * ri : 0.f;
            pr[u + 1] = m.y ? v.y * ri : 0.f;
            pr[u + 2] = m.z ? v.z * ri : 0.f;
            pr[u + 3] = m.w ? v.w * ri : 0.f;
        }
    }
    __syncthreads();

    #define F_ISSUE(buf, src, kk) {                                         \
        _Pragma("unroll")                                                   \
        for (int u = 0; u < 2; u++) {                                       \
            int gid = u * 256 + t, row = gid >> 5, ch2 = gid & 31;          \
            cpa16(bB[buf] + (row * 136 + ch2 * 4) * 4, (src) + (size_t)((kk) + row) * DD + ch2 * 4); \
        }                                                                   \
        CP_COMMIT(); }

    #pragma unroll
    for (int pass = 0; pass < 2; pass++) {
        const float* Bsrc = pass ? (g_V2 + (size_t)b * LQ * DD) : (Qg + (size_t)b * LQ * DD);
        float acc[2][8][4];
        #pragma unroll
        for (int mt = 0; mt < 2; mt++)
            #pragma unroll
            for (int nt = 0; nt < 8; nt++)
                #pragma unroll
                for (int e = 0; e < 4; e++) acc[mt][nt][e] = 0.f;

        F_ISSUE(0, Bsrc, 0)
        #pragma unroll
        for (int s = 0; s < 8; s++) {
            if (s < 7) F_ISSUE((s + 1) & 1, Bsrc, (s + 1) * 16)
            if (s < 7) { CP_WAIT(1); } else { CP_WAIT(0); }
            __syncthreads();
            const float* Bs = Bsb[s & 1];
            int kk = s * 16;
            #pragma unroll
            for (int k8 = 0; k8 < 2; k8++) {
                int kb = k8 << 3;
                uint32_t a[2][4];
                #pragma unroll
                for (int mt = 0; mt < 2; mt++) {
                    int m0 = mb + mt * 16;
                    a[mt][0] = cvt_tf32(Ps[(m0 + g) * 130 + kk + kb + tg]);
                    a[mt][1] = cvt_tf32(Ps[(m0 + g + 8) * 130 + kk + kb + tg]);
                    a[mt][2] = cvt_tf32(Ps[(m0 + g) * 130 + kk + kb + tg + 4]);
                    a[mt][3] = cvt_tf32(Ps[(m0 + g + 8) * 130 + kk + kb + tg + 4]);
                }
                #pragma unroll
                for (int nt = 0; nt < 8; nt++) {
                    uint32_t bh[2];
                    bh[0] = cvt_tf32(Bs[(kb + tg) * 136 + nb + nt * 8 + g]);
                    bh[1] = cvt_tf32(Bs[(kb + tg + 4) * 136 + nb + nt * 8 + g]);
                    mma8(acc[0][nt], a[0], bh);
                    mma8(acc[1][nt], a[1], bh);
                }
            }
            __syncthreads();
        }

        // epilogue
        #pragma unroll
        for (int mt = 0; mt < 2; mt++) {
            int r0 = i0 + mb + mt * 16 + g, r1 = r0 + 8;
            const float* c0p = Cg + ((size_t)(b * LC + r0)) * DD;
            const float* c1p = Cg + ((size_t)(b * LC + r1)) * DD;
            float* o0 = out + ((size_t)(b * LC + r0)) * (4 * DD);
            float* o1 = out + ((size_t)(b * LC + r1)) * (4 * DD);
            #pragma unroll
            for (int nt = 0; nt < 8; nt++) {
                int d = nb + nt * 8 + 2 * tg;
                float2 c0 = *(const float2*)(c0p + d);
                float2 c1 = *(const float2*)(c1p + d);
                float* a = acc[mt][nt];
                if (pass == 0) {
                    *(float2*)(o0 + d) = c0;
                    *(float2*)(o1 + d) = c1;
                    *(float2*)(o0 + DD + d) = make_float2(a[0], a[1]);
                    *(float2*)(o1 + DD + d) = make_float2(a[2], a[3]);
                    *(float2*)(o0 + 2 * DD + d) = make_float2(c0.x * a[0], c0.y * a[1]);
                    *(float2*)(o1 + 2 * DD + d) = make_float2(c1.x * a[2], c1.y * a[3]);
                } else {
                    *(float2*)(o0 + 3 * DD + d) = make_float2(c0.x * a[0], c0.y * a[1]);
                    *(float2*)(o1 + 3 * DD + d) = make_float2(c1.x * a[2], c1.y * a[3]);
                }
            }
        }
    }
}

// ---------------- launch ----------------
extern "C" void kernel_launch(void* const* d_in, const int* in_sizes, int n_in,
                              void* d_out, int out_size) {
    const float* C     = (const float*)d_in[0];
    const float* Q     = (const float*)d_in[1];
    const int*   Cmask = (const int*)d_in[2];
    const int*   Qmask = (const int*)d_in[3];
    const float* w_c   = (const float*)d_in[4];
    const float* w_q   = (const float*)d_in[5];
    const float* w_mul = (const float*)d_in[6];
    const float* bias  = (const float*)d_in[7];
    float* out = (float*)d_out;

    cudaFuncSetAttribute(s_kernel, cudaFuncAttributeMaxDynamicSharedMemorySize, S_DYN);
    cudaFuncSetAttribute(v2_kernel, cudaFuncAttributeMaxDynamicSharedMemorySize, V2_DYN);
    cudaFuncSetAttribute(final_kernel, cudaFuncAttributeMaxDynamicSharedMemorySize, F_DYN);

    s_kernel<<<BB * 8, 256, S_DYN>>>(C, Q, w_mul, w_c, w_q, bias, Qmask, Cmask);
    colmerge_kernel<<<(BB * LQ + 255) / 256, 256>>>();
    v2_kernel<<<BB * 4, 256, V2_DYN>>>(C, Cmask);
    v2reduce_kernel<<<(BB * LQ * DD / 4 + 255) / 256, 256>>>();
    final_kernel<<<BB * 8, 256, F_DYN>>>(C, Q, Qmask, out);
}